// round 5
// baseline (speedup 1.0000x reference)
#include <cuda_runtime.h>
#include <math.h>

// Problem dims
#define T_ 8
#define B_ 32
#define D_ 768
#define M_ 8
#define S_ 2
#define L_ 2
#define H_ 8
#define HD_ 96
#define d_ 384
#define P_ 16          // M_*S_
#define U_ 32          // P_*L_
#define KVROWS 256     // M_*B_
#define KVN 1536       // 2*D_

// ---------------- device state / scratch ----------------
__device__ float g_mem[M_*B_*D_];
__device__ float g_qall[(long)M_*T_*B_*D_];
__device__ float g_kv[(long)M_*KVROWS*KVN];
__device__ float g_o[M_*B_*D_];
__device__ float g_h[P_*B_*d_];
__device__ float g_pa[U_*B_*d_];
__device__ float g_pr[U_*B_*d_];
__device__ float g_dp[U_*B_*d_];
__device__ float g_sr[U_*B_*d_];
__device__ float g_gb[U_*B_*d_];
__device__ float g_W [(long)U_*d_*d_];
__device__ float g_Wr[(long)U_*d_*d_];
__device__ float g_t1[U_*B_*d_];
__device__ float g_nt[U_*B_*3*d_];
__device__ float g_mod[U_*B_*d_];
__device__ float g_asm[2*U_*B_*d_];
__device__ float g_C[(long)2*U_*d_*d_];
__device__ float g_tmp[U_*B_*d_];
__device__ float g_outpre[M_*B_*D_];

// ---------------- f32x2 helpers ----------------
__device__ __forceinline__ void fma2(unsigned long long& d, unsigned long long a, unsigned long long b) {
    asm("fma.rn.f32x2 %0, %1, %2, %0;" : "+l"(d) : "l"(a), "l"(b));
}
__device__ __forceinline__ float2 unpack2(unsigned long long v) {
    float2 f;
    asm("mov.b64 {%0, %1}, %2;" : "=f"(f.x), "=f"(f.y) : "l"(v));
    return f;
}

// ---------------- generic batched tiled GEMM (f32x2, dup-A smem, dbl-buffer) -
// C[z][i][j] = act( scale*(sum_k opA(A)[i][k]*opB(W)[k][j] + bias[z][j]) + add[z][i][j] )
// TRANSA: A stored [K, M] row stride lda. else [M, K] row stride lda.
// TRANSB: W row-major [N, K]. else W row-major [K, N].
// AMODE=1: A element (z,i,k) read from h-layout: A[((z*2 + k/384)*B_ + i)*384 + k%384]
// CMODE=1: C element (z,i,j) written to h-layout.
// zwrap!=0: weight batch index = z % zwrap.
// Tile BM=32, BN=64, BK=16; 128 threads; thread computes 4x4.
// As2 rows hold duplicated pairs: As2[kk][2*r .. 2*r+1] = A value for row r.
#define A2_ST 68
#define B_ST  68
template<int AMODE, int CMODE, bool TRANSA, bool TRANSB>
__global__ __launch_bounds__(128) void gemm2_k(
                        const float* __restrict__ A, long aB, int lda,
                        const float* __restrict__ W, long wB, int zwrap,
                        const float* __restrict__ bias, long bB,
                        const float* __restrict__ add, long adB,
                        float* __restrict__ C, long cB,
                        int N, int K, float scale, int relu)
{
    __shared__ float As2[2][16*A2_ST];
    __shared__ float Bs [2][16*B_ST];
    const int tid = threadIdx.x;               // 128
    const int tx = tid & 15;                    // col group (4 cols)
    const int ty = tid >> 4;                    // row group (4 rows)
    const int z = blockIdx.z;
    const float* Ab = A + (long)z*aB;
    const float* Wb = W + (long)(zwrap ? (z % zwrap) : z)*wB;
    const int row0 = blockIdx.y*32, col0 = blockIdx.x*64;

    unsigned long long acc[4][2];
    #pragma unroll
    for (int r = 0; r < 4; r++) { acc[r][0] = 0ull; acc[r][1] = 0ull; }

    // per-thread load coords
    const int a_kk = tid >> 3, a_r4 = (tid & 7)*4;        // TRANSA
    const int a_r  = tid >> 2, a_kc = (tid & 3)*4;        // normal A
    float4 ra, rb0, rb1;

    // ---- load helpers (into registers) ----
    auto loadA = [&](int k0) {
        if (TRANSA) {
            ra = *(const float4*)&Ab[(long)(k0 + a_kk)*lda + row0 + a_r4];
        } else if (AMODE) {
            int k = k0 + a_kc; int sh = k / d_, kr = k % d_;
            ra = *(const float4*)&A[(((long)z*2 + sh)*B_ + row0 + a_r)*d_ + kr];
        } else {
            ra = *(const float4*)&Ab[(long)(row0 + a_r)*lda + k0 + a_kc];
        }
    };
    auto loadB = [&](int k0) {
        if (TRANSB) {
            int j = tid >> 2, kc = (tid & 3)*4;
            rb0 = *(const float4*)&Wb[(long)(col0 + j)*K + k0 + kc];
            rb1 = *(const float4*)&Wb[(long)(col0 + j + 32)*K + k0 + kc];
        } else {
            int kk = tid >> 4, j4 = (tid & 15)*4;
            rb0 = *(const float4*)&Wb[(long)(k0 + kk)*N + col0 + j4];
            rb1 = *(const float4*)&Wb[(long)(k0 + kk + 8)*N + col0 + j4];
        }
    };
    auto storeT = [&](int buf) {
        // A: duplicated pairs
        if (TRANSA) {
            float* dst = &As2[buf][a_kk*A2_ST + a_r4*2];
            *(float4*)&dst[0] = make_float4(ra.x, ra.x, ra.y, ra.y);
            *(float4*)&dst[4] = make_float4(ra.z, ra.z, ra.w, ra.w);
        } else {
            *(float2*)&As2[buf][(a_kc+0)*A2_ST + a_r*2] = make_float2(ra.x, ra.x);
            *(float2*)&As2[buf][(a_kc+1)*A2_ST + a_r*2] = make_float2(ra.y, ra.y);
            *(float2*)&As2[buf][(a_kc+2)*A2_ST + a_r*2] = make_float2(ra.z, ra.z);
            *(float2*)&As2[buf][(a_kc+3)*A2_ST + a_r*2] = make_float2(ra.w, ra.w);
        }
        // B
        if (TRANSB) {
            int j = tid >> 2, kc = (tid & 3)*4;
            Bs[buf][(kc+0)*B_ST + j] = rb0.x;
            Bs[buf][(kc+1)*B_ST + j] = rb0.y;
            Bs[buf][(kc+2)*B_ST + j] = rb0.z;
            Bs[buf][(kc+3)*B_ST + j] = rb0.w;
            Bs[buf][(kc+0)*B_ST + j + 32] = rb1.x;
            Bs[buf][(kc+1)*B_ST + j + 32] = rb1.y;
            Bs[buf][(kc+2)*B_ST + j + 32] = rb1.z;
            Bs[buf][(kc+3)*B_ST + j + 32] = rb1.w;
        } else {
            int kk = tid >> 4, j4 = (tid & 15)*4;
            *(float4*)&Bs[buf][kk*B_ST + j4] = rb0;
            *(float4*)&Bs[buf][(kk+8)*B_ST + j4] = rb1;
        }
    };

    const int nk = K >> 4;
    loadA(0); loadB(0);
    storeT(0);
    __syncthreads();

    for (int kt = 0; kt < nk; kt++) {
        const int cur = kt & 1;
        if (kt + 1 < nk) { loadA((kt+1)<<4); loadB((kt+1)<<4); }
        #pragma unroll
        for (int kk = 0; kk < 16; kk++) {
            const float* abase = &As2[cur][kk*A2_ST + ty*8];
            ulonglong2 ap0 = *(const ulonglong2*)abase;        // rows ty*4+0, +1
            ulonglong2 ap1 = *(const ulonglong2*)(abase + 4);  // rows ty*4+2, +3
            ulonglong2 bv  = *(const ulonglong2*)&Bs[cur][kk*B_ST + tx*4];
            fma2(acc[0][0], ap0.x, bv.x); fma2(acc[0][1], ap0.x, bv.y);
            fma2(acc[1][0], ap0.y, bv.x); fma2(acc[1][1], ap0.y, bv.y);
            fma2(acc[2][0], ap1.x, bv.x); fma2(acc[2][1], ap1.x, bv.y);
            fma2(acc[3][0], ap1.y, bv.x); fma2(acc[3][1], ap1.y, bv.y);
        }
        if (kt + 1 < nk) {
            storeT(cur ^ 1);
            __syncthreads();
        }
    }

    float* Cb = C + (long)z*cB;
    const int colb = col0 + tx*4;
    #pragma unroll
    for (int r = 0; r < 4; r++) {
        int row = row0 + ty*4 + r;
        float2 v0 = unpack2(acc[r][0]);
        float2 v1 = unpack2(acc[r][1]);
        float v[4] = {v0.x, v0.y, v1.x, v1.y};
        #pragma unroll
        for (int c = 0; c < 4; c++) {
            if (bias) v[c] += bias[(long)z*bB + colb + c];
            v[c] *= scale;
            if (add)  v[c] += add[(long)z*adB + (long)row*N + colb + c];
            if (relu) v[c] = fmaxf(v[c], 0.f);
        }
        if (CMODE) {
            int sh = colb / d_, jr = colb % d_;
            float* dst = C + (((long)z*2 + sh)*B_ + row)*d_ + jr;
            *(float4*)dst = make_float4(v[0], v[1], v[2], v[3]);
        } else {
            *(float4*)&Cb[(long)row*N + colb] = make_float4(v[0], v[1], v[2], v[3]);
        }
    }
}

// ---------------- attention core (warp per (h,b,m)) ----------------
__global__ void attn2_k(int t)
{
    int gw = (blockIdx.x*blockDim.x + threadIdx.x) >> 5;
    int lane = threadIdx.x & 31;
    int h = gw & 7;
    int b = (gw >> 3) & 31;
    int m = gw >> 8;
    const float* qb = g_qall + ((long)m*T_*B_ + t*B_ + b)*D_ + h*HD_;
    float q0 = qb[lane], q1 = qb[lane + 32], q2 = qb[lane + 64];
    float a[M_];
    #pragma unroll
    for (int s = 0; s < M_; s++) {
        const float* kb = g_kv + ((long)m*KVROWS + s*B_ + b)*KVN + h*HD_;
        float p = q0*kb[lane] + q1*kb[lane + 32] + q2*kb[lane + 64];
        #pragma unroll
        for (int o = 16; o > 0; o >>= 1) p += __shfl_xor_sync(0xffffffffu, p, o);
        a[s] = p;
    }
    float mx = -1e30f;
    #pragma unroll
    for (int s = 0; s < M_; s++) mx = fmaxf(mx, a[s]);
    float sum = 0.f;
    #pragma unroll
    for (int s = 0; s < M_; s++) { a[s] = __expf(a[s] - mx); sum += a[s]; }
    float inv = 1.f / sum;
    float o0 = 0.f, o1 = 0.f, o2 = 0.f;
    #pragma unroll
    for (int s = 0; s < M_; s++) {
        const float* vb = g_kv + ((long)m*KVROWS + s*B_ + b)*KVN + D_ + h*HD_;
        float av = a[s]*inv;
        o0 += av*vb[lane]; o1 += av*vb[lane + 32]; o2 += av*vb[lane + 64];
    }
    float* ob = g_o + ((long)(m*B_ + b))*D_ + h*HD_;
    ob[lane] = o0; ob[lane + 32] = o1; ob[lane + 64] = o2;
}

// ---------------- plastic layer kernels (batched over U_ units) --------------
__global__ void gates_k(const float* __restrict__ alpha)
{
    int idx = blockIdx.x*256 + threadIdx.x;
    if (idx >= U_*B_*d_) return;
    int j = idx % d_; int b = (idx/d_) % B_; int u = idx/(B_*d_);
    const float* nt = g_nt + ((long)(u*B_ + b))*3*d_ + j*3;
    float pd = nt[0], ps = nt[1], pg = nt[2];
    float inv = 1.f / fmaxf(ps, 1e-6f);
    float dpv = tanhf(g_dp[idx] + pd*inv);
    float srv = 1.f/(1.f + __expf(-(g_sr[idx] + ps)));
    float gbv = 1.f/(1.f + __expf(-(g_gb[idx] + pg*inv)));
    g_dp[idx] = dpv; g_sr[idx] = srv; g_gb[idx] = gbv;
    g_mod[idx] = alpha[(long)u*d_ + j] * dpv * srv;
}

__global__ void rsm_k()   // row softmax of pa (which=0) / pr (which=1) over d_
{
    int row = blockIdx.x;      // 0..U_*B_-1
    int which = blockIdx.y;
    const float* src = (which ? g_pr : g_pa) + (long)row*d_;
    float* dst = g_asm + (long)which*U_*B_*d_ + (long)row*d_;
    int u = threadIdx.x;       // 128
    __shared__ float red[128];
    float v0 = src[u], v1 = src[u + 128], v2 = src[u + 256];
    float mx = fmaxf(v0, fmaxf(v1, v2));
    red[u] = mx; __syncthreads();
    #pragma unroll
    for (int o = 64; o > 0; o >>= 1) { if (u < o) red[u] = fmaxf(red[u], red[u + o]); __syncthreads(); }
    mx = red[0]; __syncthreads();
    float e0 = __expf(v0 - mx), e1 = __expf(v1 - mx), e2 = __expf(v2 - mx);
    red[u] = e0 + e1 + e2; __syncthreads();
    #pragma unroll
    for (int o = 64; o > 0; o >>= 1) { if (u < o) red[u] += red[u + o]; __syncthreads(); }
    float inv = 1.f / red[0];
    dst[u] = e0*inv; dst[u + 128] = e1*inv; dst[u + 256] = e2*inv;
}

// W_new[i][j] = W*(1-sd[i]) + rowsoftmax(W)[i][j]*C[i][j]   (sd computed in-block)
__global__ void wupd_k(const float* __restrict__ decay)
{
    int i = blockIdx.x, u = blockIdx.y, which = blockIdx.z;
    float* Wp = (which ? g_Wr : g_W) + ((long)u*d_ + i)*d_;
    const float* Cp = g_C + ((long)(which*U_ + u)*d_ + i)*d_;
    int t = threadIdx.x;  // 128
    __shared__ float red[128];
    __shared__ float sdsh;
    if (t < 32) {
        float v = g_gb[((long)u*B_ + t)*d_ + i];
        #pragma unroll
        for (int o = 16; o > 0; o >>= 1) v += __shfl_xor_sync(0xffffffffu, v, o);
        if (t == 0) {
            float s = v*(1.f/B_);
            sdsh = decay[(long)u*d_ + i] * (1.f/(1.f + __expf(-s)));
        }
    }
    float w0 = Wp[t], w1 = Wp[t + 128], w2 = Wp[t + 256];
    float mx = fmaxf(w0, fmaxf(w1, w2));
    red[t] = mx; __syncthreads();
    #pragma unroll
    for (int o = 64; o > 0; o >>= 1) { if (t < o) red[t] = fmaxf(red[t], red[t + o]); __syncthreads(); }
    mx = red[0]; __syncthreads();
    float e0 = __expf(w0 - mx), e1 = __expf(w1 - mx), e2 = __expf(w2 - mx);
    red[t] = e0 + e1 + e2; __syncthreads();
    #pragma unroll
    for (int o = 64; o > 0; o >>= 1) { if (t < o) red[t] += red[t + o]; __syncthreads(); }
    float invs = 1.f / red[0];
    float om = 1.f - sdsh;
    Wp[t]       = w0*om + e0*invs*Cp[t];
    Wp[t + 128] = w1*om + e1*invs*Cp[t + 128];
    Wp[t + 256] = w2*om + e2*invs*Cp[t + 256];
}

// ---------------- LayerNorm ----------------
__global__ void ln_k(const float* __restrict__ in,
                     float* __restrict__ out1, long o1Group,
                     float* __restrict__ out2,
                     const float* __restrict__ gam, const float* __restrict__ bet,
                     long gGroup, int N)
{
    int row = blockIdx.x;
    int u = threadIdx.x;   // 128
    int grp = row / B_, rb = row % B_;
    const float* x = in + (long)row*N;
    int nper = N / 128;    // 3 or 6
    float vals[6];
    float s = 0.f;
    for (int t = 0; t < nper; t++) { vals[t] = x[u + t*128]; s += vals[t]; }
    __shared__ float red[128];
    red[u] = s; __syncthreads();
    #pragma unroll
    for (int o = 64; o > 0; o >>= 1) { if (u < o) red[u] += red[u + o]; __syncthreads(); }
    float mu = red[0] / N; __syncthreads();
    float sq = 0.f;
    for (int t = 0; t < nper; t++) { float dv = vals[t] - mu; sq += dv*dv; }
    red[u] = sq; __syncthreads();
    #pragma unroll
    for (int o = 64; o > 0; o >>= 1) { if (u < o) red[u] += red[u + o]; __syncthreads(); }
    float rstd = rsqrtf(red[0] / N + 1e-5f);
    float* o1 = out1 + (long)grp*o1Group + (long)rb*N;
    const float* gp = gam + (long)grp*gGroup;
    const float* bp = bet + (long)grp*gGroup;
    for (int t = 0; t < nper; t++) {
        int j = u + t*128;
        float y = (vals[t] - mu)*rstd*gp[j] + bp[j];
        o1[j] = y;
        if (out2) out2[(long)row*N + j] = y;
    }
}

__global__ void clear_k()
{
    long idx = (long)blockIdx.x*256 + threadIdx.x;
    if (idx < (long)U_*B_*d_) {
        g_pa[idx] = 0.f; g_pr[idx] = 0.f; g_dp[idx] = 0.f; g_sr[idx] = 0.f; g_gb[idx] = 0.f;
    }
}

// ---------------- host launcher ----------------
extern "C" void kernel_launch(void* const* d_in, const int* in_sizes, int n_in,
                              void* d_out, int out_size)
{
    const float* x          = (const float*)d_in[0];
    const float* mem0       = (const float*)d_in[1];
    const float* attn_in_w  = (const float*)d_in[2];
    const float* attn_in_b  = (const float*)d_in[3];
    const float* attn_out_w = (const float*)d_in[4];
    const float* attn_out_b = (const float*)d_in[5];
    const float* heb_w      = (const float*)d_in[6];
    const float* heb_rw     = (const float*)d_in[7];
    const float* alpha      = (const float*)d_in[8];
    const float* decay      = (const float*)d_in[9];
    const float* ln_act_g   = (const float*)d_in[10];
    const float* ln_act_b   = (const float*)d_in[11];
    const float* ln_rec_g   = (const float*)d_in[12];
    const float* ln_rec_b   = (const float*)d_in[13];
    const float* pred_w1    = (const float*)d_in[14];
    const float* pred_b1    = (const float*)d_in[15];
    const float* pred_w2    = (const float*)d_in[16];
    const float* pred_b2    = (const float*)d_in[17];
    const float* out_w      = (const float*)d_in[18];
    const float* out_b      = (const float*)d_in[19];
    const float* ln_out_g   = (const float*)d_in[20];
    const float* ln_out_b   = (const float*)d_in[21];

    float *pmem, *pqall, *pkv, *po, *ph, *ppa, *ppr, *pt1, *pnt, *ptmp,
          *poutpre, *pW, *pWr, *pasm, *pmod, *pC;
    cudaGetSymbolAddress((void**)&pmem,    g_mem);
    cudaGetSymbolAddress((void**)&pqall,   g_qall);
    cudaGetSymbolAddress((void**)&pkv,     g_kv);
    cudaGetSymbolAddress((void**)&po,      g_o);
    cudaGetSymbolAddress((void**)&ph,      g_h);
    cudaGetSymbolAddress((void**)&ppa,     g_pa);
    cudaGetSymbolAddress((void**)&ppr,     g_pr);
    cudaGetSymbolAddress((void**)&pt1,     g_t1);
    cudaGetSymbolAddress((void**)&pnt,     g_nt);
    cudaGetSymbolAddress((void**)&ptmp,    g_tmp);
    cudaGetSymbolAddress((void**)&poutpre, g_outpre);
    cudaGetSymbolAddress((void**)&pW,      g_W);
    cudaGetSymbolAddress((void**)&pWr,     g_Wr);
    cudaGetSymbolAddress((void**)&pasm,    g_asm);
    cudaGetSymbolAddress((void**)&pmod,    g_mod);
    cudaGetSymbolAddress((void**)&pC,      g_C);

    const float qscale = 1.f / sqrtf((float)HD_);

    // init state
    cudaMemcpyAsync(pW,  heb_w,  sizeof(float)*(long)U_*d_*d_, cudaMemcpyDeviceToDevice, 0);
    cudaMemcpyAsync(pWr, heb_rw, sizeof(float)*(long)U_*d_*d_, cudaMemcpyDeviceToDevice, 0);
    cudaMemcpyAsync(pmem, mem0,  sizeof(float)*M_*B_*D_,       cudaMemcpyDeviceToDevice, 0);
    clear_k<<<(U_*B_*d_ + 255)/256, 256>>>();

    // q for all timesteps: per m, (T*B x 768) = x @ wq^T * qscale
    gemm2_k<0,0,false,true><<<dim3(12, 8, M_), 128>>>(x, 0, D_,
        attn_in_w, (long)3*D_*D_, 0, attn_in_b, (long)3*D_, nullptr, 0,
        pqall, (long)T_*B_*D_, D_, D_, qscale, 0);

    for (int t = 0; t < T_; t++) {
        // ---- Hebbian chain (batched over U_=32 units; uses only prev-step state)
        gemm2_k<0,0,false,false><<<dim3(6, 1, U_), 128>>>(ppa, (long)B_*d_, d_,
            pred_w1, (long)d_*d_, 0, pred_b1, (long)d_, nullptr, 0,
            pt1, (long)B_*d_, d_, d_, 1.f, 1);
        gemm2_k<0,0,false,false><<<dim3(18, 1, U_), 128>>>(pt1, (long)B_*d_, d_,
            pred_w2, (long)d_*3*d_, 0, pred_b2, (long)3*d_, nullptr, 0,
            pnt, (long)B_*3*d_, 3*d_, d_, 1.f, 0);
        gates_k<<<(U_*B_*d_ + 255)/256, 256>>>(alpha);
        rsm_k<<<dim3(U_*B_, 2), 128>>>();
        // C[z] = (1/B) * asm[z]^T @ mod[z%U_]   z in [0, 2U)
        gemm2_k<0,0,true,false><<<dim3(6, 12, 2*U_), 128>>>(pasm, (long)B_*d_, d_,
            pmod, (long)B_*d_, U_, nullptr, 0, nullptr, 0,
            pC, (long)d_*d_, d_, B_, 1.f/B_, 0);
        wupd_k<<<dim3(d_, U_, 2), 128>>>(decay);
        // rec_pre = pa @ Wr_new ; pr = LN(rec_pre)
        gemm2_k<0,0,false,false><<<dim3(6, 1, U_), 128>>>(ppa, (long)B_*d_, d_,
            pWr, (long)d_*d_, 0, nullptr, 0, nullptr, 0,
            ptmp, (long)B_*d_, d_, d_, 1.f, 0);
        ln_k<<<U_*B_, 128>>>(ptmp, ppr, (long)B_*d_, nullptr,
            ln_rec_g, ln_rec_b, (long)d_, d_);

        // ---- attention chain
        gemm2_k<0,0,false,true><<<dim3(24, 8, M_), 128>>>(pmem, 0, D_,
            attn_in_w + (long)D_*D_, (long)3*D_*D_, 0, attn_in_b + D_, (long)3*D_, nullptr, 0,
            pkv, (long)KVROWS*KVN, KVN, D_, 1.f, 0);
        attn2_k<<<256, 256>>>(t);
        // h = scatter( o @ out_w^T + out_b )   (CMODE epilogue does a2h)
        gemm2_k<0,1,false,true><<<dim3(12, 1, M_), 128>>>(po, (long)B_*D_, D_,
            attn_out_w, (long)D_*D_, 0, attn_out_b, (long)D_, nullptr, 0,
            ph, 0, D_, D_, 1.f, 0);

        // ---- per-layer activation (serial over l; z = p in [0,16))
        for (int l = 0; l < L_; l++) {
            gemm2_k<0,0,false,false><<<dim3(6, 1, P_), 128>>>(ph, (long)B_*d_, d_,
                pW + (long)l*d_*d_, (long)L_*d_*d_, 0, nullptr, 0,
                ppr + (long)l*B_*d_, (long)L_*B_*d_,
                ptmp, (long)B_*d_, d_, d_, 1.f, 1);
            ln_k<<<P_*B_, 128>>>(ptmp, ppa + (long)l*B_*d_, (long)L_*B_*d_, ph,
                ln_act_g + (long)l*d_, ln_act_b + (long)l*d_, (long)L_*d_, d_);
        }

        // ---- output projection (AMODE prologue does h2cat gather)
        gemm2_k<1,0,false,true><<<dim3(12, 1, M_), 128>>>(ph, 0, 0,
            out_w, (long)D_*D_, 0, out_b, (long)D_, nullptr, 0,
            poutpre, (long)B_*D_, D_, D_, 1.f, 0);
        ln_k<<<M_*B_, 128>>>(poutpre, pmem, (long)B_*D_, nullptr,
            ln_out_g, ln_out_b, (long)D_, D_);
    }

    cudaMemcpyAsync(d_out, pmem, sizeof(float)*M_*B_*D_, cudaMemcpyDeviceToDevice, 0);
}

// round 6
// speedup vs baseline: 1.2224x; 1.2224x over previous
#include <cuda_runtime.h>
#include <math.h>

// Problem dims
#define T_ 8
#define B_ 32
#define D_ 768
#define M_ 8
#define S_ 2
#define L_ 2
#define H_ 8
#define HD_ 96
#define d_ 384
#define P_ 16          // M_*S_
#define U_ 32          // P_*L_
#define KVROWS 256     // M_*B_
#define KVN 1536       // 2*D_

// ---------------- device state / scratch ----------------
__device__ float g_mem[M_*B_*D_];
__device__ float g_qall[(long)M_*T_*B_*D_];
__device__ float g_kv[(long)M_*KVROWS*KVN];
__device__ float g_o[M_*B_*D_];
__device__ float g_h[P_*B_*d_];
__device__ float g_pa[U_*B_*d_];
__device__ float g_pr[U_*B_*d_];
__device__ float g_dp[U_*B_*d_];
__device__ float g_sr[U_*B_*d_];
__device__ float g_gb[U_*B_*d_];
__device__ float g_W [(long)U_*d_*d_];
__device__ float g_Wr[(long)U_*d_*d_];
__device__ float g_t1[U_*B_*d_];
__device__ float g_nt[U_*B_*3*d_];
__device__ float g_mod[U_*B_*d_];
__device__ float g_asm[2*U_*B_*d_];
__device__ float g_C[(long)2*U_*d_*d_];
__device__ float g_tmp[U_*B_*d_];
__device__ float g_act[P_*B_*d_];
__device__ float g_outpre[M_*B_*D_];

// ---------------- f32x2 helpers ----------------
__device__ __forceinline__ unsigned long long pack2(float x, float y) {
    unsigned long long r;
    asm("mov.b64 %0, {%1, %2};" : "=l"(r) : "f"(x), "f"(y));
    return r;
}
__device__ __forceinline__ void fma2(unsigned long long& d, unsigned long long a, unsigned long long b) {
    asm("fma.rn.f32x2 %0, %1, %2, %0;" : "+l"(d) : "l"(a), "l"(b));
}
__device__ __forceinline__ float2 unpack2(unsigned long long v) {
    float2 f;
    asm("mov.b64 {%0, %1}, %2;" : "=f"(f.x), "=f"(f.y) : "l"(v));
    return f;
}

// ---------------- generic batched tiled GEMM (R4-proven f32x2, 4x4 tile) -----
#define AS_STRIDE 36
#define BS_STRIDE 68
template<int AMODE, int CMODE, bool TRANSA, bool TRANSB>
__global__ __launch_bounds__(128) void gemm2_k(
                        const float* __restrict__ A, long aB, int lda,
                        const float* __restrict__ W, long wB, int zwrap,
                        const float* __restrict__ bias, long bB,
                        const float* __restrict__ add, long adB,
                        float* __restrict__ C, long cB,
                        int N, int K, float scale, int relu)
{
    __shared__ float As[16*AS_STRIDE];
    __shared__ float Bs[16*BS_STRIDE];
    const int tid = threadIdx.x;               // 128
    const int tx = tid & 15;                    // col group (4 cols)
    const int ty = tid >> 4;                    // row group (4 rows)
    const int z = blockIdx.z;
    const float* Ab = A + (long)z*aB;
    const float* Wb = W + (long)(zwrap ? (z % zwrap) : z)*wB;
    const int row0 = blockIdx.y*32, col0 = blockIdx.x*64;

    unsigned long long acc[4][2];
    #pragma unroll
    for (int r = 0; r < 4; r++) { acc[r][0] = 0ull; acc[r][1] = 0ull; }

    for (int k0 = 0; k0 < K; k0 += 16) {
        // A tile -> As[kk][row]
        if (TRANSA) {
            int kk = tid >> 3, r4 = (tid & 7)*4;
            float4 av = *(const float4*)&Ab[(long)(k0 + kk)*lda + row0 + r4];
            *(float4*)&As[kk*AS_STRIDE + r4] = av;
        } else {
            int r = tid >> 2, kc = (tid & 3)*4;
            float4 av;
            if (AMODE) {
                int k = k0 + kc; int sh = k / d_, kr = k % d_;
                av = *(const float4*)&A[(((long)z*2 + sh)*B_ + row0 + r)*d_ + kr];
            } else {
                av = *(const float4*)&Ab[(long)(row0 + r)*lda + k0 + kc];
            }
            As[(kc+0)*AS_STRIDE + r] = av.x;
            As[(kc+1)*AS_STRIDE + r] = av.y;
            As[(kc+2)*AS_STRIDE + r] = av.z;
            As[(kc+3)*AS_STRIDE + r] = av.w;
        }
        // B tile -> Bs[kk][j]   (16 x 64)
        #pragma unroll
        for (int it = 0; it < 2; it++) {
            int e = tid + it*128;
            if (TRANSB) {
                int j = e >> 2, kc = (e & 3)*4;
                float4 wv = *(const float4*)&Wb[(long)(col0 + j)*K + k0 + kc];
                Bs[(kc+0)*BS_STRIDE + j] = wv.x;
                Bs[(kc+1)*BS_STRIDE + j] = wv.y;
                Bs[(kc+2)*BS_STRIDE + j] = wv.z;
                Bs[(kc+3)*BS_STRIDE + j] = wv.w;
            } else {
                int kk = e >> 4, j4 = (e & 15)*4;
                float4 wv = *(const float4*)&Wb[(long)(k0 + kk)*N + col0 + j4];
                *(float4*)&Bs[kk*BS_STRIDE + j4] = wv;
            }
        }
        __syncthreads();
        #pragma unroll
        for (int kk = 0; kk < 16; kk++) {
            float4 a = *(const float4*)&As[kk*AS_STRIDE + ty*4];
            unsigned long long b0 = *(const unsigned long long*)&Bs[kk*BS_STRIDE + tx*4];
            unsigned long long b1 = *(const unsigned long long*)&Bs[kk*BS_STRIDE + tx*4 + 2];
            unsigned long long a0 = pack2(a.x, a.x);
            unsigned long long a1 = pack2(a.y, a.y);
            unsigned long long a2 = pack2(a.z, a.z);
            unsigned long long a3 = pack2(a.w, a.w);
            fma2(acc[0][0], a0, b0); fma2(acc[0][1], a0, b1);
            fma2(acc[1][0], a1, b0); fma2(acc[1][1], a1, b1);
            fma2(acc[2][0], a2, b0); fma2(acc[2][1], a2, b1);
            fma2(acc[3][0], a3, b0); fma2(acc[3][1], a3, b1);
        }
        __syncthreads();
    }

    float* Cb = C + (long)z*cB;
    const int colb = col0 + tx*4;
    #pragma unroll
    for (int r = 0; r < 4; r++) {
        int row = row0 + ty*4 + r;
        float2 v0 = unpack2(acc[r][0]);
        float2 v1 = unpack2(acc[r][1]);
        float v[4] = {v0.x, v0.y, v1.x, v1.y};
        #pragma unroll
        for (int c = 0; c < 4; c++) {
            if (bias) v[c] += bias[(long)z*bB + colb + c];
            v[c] *= scale;
            if (add)  v[c] += add[(long)z*adB + (long)row*N + colb + c];
            if (relu) v[c] = fmaxf(v[c], 0.f);
        }
        if (CMODE) {
            int sh = colb / d_, jr = colb % d_;
            float* dst = C + (((long)z*2 + sh)*B_ + row)*d_ + jr;
            *(float4*)dst = make_float4(v[0], v[1], v[2], v[3]);
        } else {
            *(float4*)&Cb[(long)row*N + colb] = make_float4(v[0], v[1], v[2], v[3]);
        }
    }
}

// ---------------- attention core (warp per (h,b,m)) ----------------
__global__ void attn2_k(int t)
{
    int gw = (blockIdx.x*blockDim.x + threadIdx.x) >> 5;
    int lane = threadIdx.x & 31;
    int h = gw & 7;
    int b = (gw >> 3) & 31;
    int m = gw >> 8;
    const float* qb = g_qall + ((long)m*T_*B_ + t*B_ + b)*D_ + h*HD_;
    float q0 = qb[lane], q1 = qb[lane + 32], q2 = qb[lane + 64];
    float a[M_];
    #pragma unroll
    for (int s = 0; s < M_; s++) {
        const float* kb = g_kv + ((long)m*KVROWS + s*B_ + b)*KVN + h*HD_;
        float p = q0*kb[lane] + q1*kb[lane + 32] + q2*kb[lane + 64];
        #pragma unroll
        for (int o = 16; o > 0; o >>= 1) p += __shfl_xor_sync(0xffffffffu, p, o);
        a[s] = p;
    }
    float mx = -1e30f;
    #pragma unroll
    for (int s = 0; s < M_; s++) mx = fmaxf(mx, a[s]);
    float sum = 0.f;
    #pragma unroll
    for (int s = 0; s < M_; s++) { a[s] = __expf(a[s] - mx); sum += a[s]; }
    float inv = 1.f / sum;
    float o0 = 0.f, o1 = 0.f, o2 = 0.f;
    #pragma unroll
    for (int s = 0; s < M_; s++) {
        const float* vb = g_kv + ((long)m*KVROWS + s*B_ + b)*KVN + D_ + h*HD_;
        float av = a[s]*inv;
        o0 += av*vb[lane]; o1 += av*vb[lane + 32]; o2 += av*vb[lane + 64];
    }
    float* ob = g_o + ((long)(m*B_ + b))*D_ + h*HD_;
    ob[lane] = o0; ob[lane + 32] = o1; ob[lane + 64] = o2;
}

// ---------------- plastic layer kernels (batched over U_ units) --------------
__global__ void gates_k(const float* __restrict__ alpha)
{
    int idx = blockIdx.x*256 + threadIdx.x;
    if (idx >= U_*B_*d_) return;
    int j = idx % d_; int b = (idx/d_) % B_; int u = idx/(B_*d_);
    const float* nt = g_nt + ((long)(u*B_ + b))*3*d_ + j*3;
    float pd = nt[0], ps = nt[1], pg = nt[2];
    float inv = 1.f / fmaxf(ps, 1e-6f);
    float dpv = tanhf(g_dp[idx] + pd*inv);
    float srv = 1.f/(1.f + __expf(-(g_sr[idx] + ps)));
    float gbv = 1.f/(1.f + __expf(-(g_gb[idx] + pg*inv)));
    g_dp[idx] = dpv; g_sr[idx] = srv; g_gb[idx] = gbv;
    g_mod[idx] = alpha[(long)u*d_ + j] * dpv * srv;
}

__global__ void rsm_k()   // row softmax of pa (which=0) / pr (which=1) over d_
{
    int row = blockIdx.x;      // 0..U_*B_-1
    int which = blockIdx.y;
    const float* src = (which ? g_pr : g_pa) + (long)row*d_;
    float* dst = g_asm + (long)which*U_*B_*d_ + (long)row*d_;
    int u = threadIdx.x;       // 128
    __shared__ float red[128];
    float v0 = src[u], v1 = src[u + 128], v2 = src[u + 256];
    float mx = fmaxf(v0, fmaxf(v1, v2));
    red[u] = mx; __syncthreads();
    #pragma unroll
    for (int o = 64; o > 0; o >>= 1) { if (u < o) red[u] = fmaxf(red[u], red[u + o]); __syncthreads(); }
    mx = red[0]; __syncthreads();
    float e0 = __expf(v0 - mx), e1 = __expf(v1 - mx), e2 = __expf(v2 - mx);
    red[u] = e0 + e1 + e2; __syncthreads();
    #pragma unroll
    for (int o = 64; o > 0; o >>= 1) { if (u < o) red[u] += red[u + o]; __syncthreads(); }
    float inv = 1.f / red[0];
    dst[u] = e0*inv; dst[u + 128] = e1*inv; dst[u + 256] = e2*inv;
}

// W_new[i][j] = W*(1-sd[i]) + rowsoftmax(W)[i][j]*C[i][j]   (sd computed in-block)
__global__ void wupd_k(const float* __restrict__ decay)
{
    int i = blockIdx.x, u = blockIdx.y, which = blockIdx.z;
    float* Wp = (which ? g_Wr : g_W) + ((long)u*d_ + i)*d_;
    const float* Cp = g_C + ((long)(which*U_ + u)*d_ + i)*d_;
    int t = threadIdx.x;  // 128
    __shared__ float red[128];
    __shared__ float sdsh;
    if (t < 32) {
        float v = g_gb[((long)u*B_ + t)*d_ + i];
        #pragma unroll
        for (int o = 16; o > 0; o >>= 1) v += __shfl_xor_sync(0xffffffffu, v, o);
        if (t == 0) {
            float s = v*(1.f/B_);
            sdsh = decay[(long)u*d_ + i] * (1.f/(1.f + __expf(-s)));
        }
    }
    float w0 = Wp[t], w1 = Wp[t + 128], w2 = Wp[t + 256];
    float mx = fmaxf(w0, fmaxf(w1, w2));
    red[t] = mx; __syncthreads();
    #pragma unroll
    for (int o = 64; o > 0; o >>= 1) { if (t < o) red[t] = fmaxf(red[t], red[t + o]); __syncthreads(); }
    mx = red[0]; __syncthreads();
    float e0 = __expf(w0 - mx), e1 = __expf(w1 - mx), e2 = __expf(w2 - mx);
    red[t] = e0 + e1 + e2; __syncthreads();
    #pragma unroll
    for (int o = 64; o > 0; o >>= 1) { if (t < o) red[t] += red[t + o]; __syncthreads(); }
    float invs = 1.f / red[0];
    float om = 1.f - sdsh;
    Wp[t]       = w0*om + e0*invs*Cp[t];
    Wp[t + 128] = w1*om + e1*invs*Cp[t + 128];
    Wp[t + 256] = w2*om + e2*invs*Cp[t + 256];
}

// ---------------- LayerNorm ----------------
__global__ void ln_k(const float* __restrict__ in,
                     float* __restrict__ out1, long o1Group,
                     float* __restrict__ out2,
                     const float* __restrict__ gam, const float* __restrict__ bet,
                     long gGroup, int N)
{
    int row = blockIdx.x;
    int u = threadIdx.x;   // 128
    int grp = row / B_, rb = row % B_;
    const float* x = in + (long)row*N;
    int nper = N / 128;    // 3 or 6
    float vals[6];
    float s = 0.f;
    for (int t = 0; t < nper; t++) { vals[t] = x[u + t*128]; s += vals[t]; }
    __shared__ float red[128];
    red[u] = s; __syncthreads();
    #pragma unroll
    for (int o = 64; o > 0; o >>= 1) { if (u < o) red[u] += red[u + o]; __syncthreads(); }
    float mu = red[0] / N; __syncthreads();
    float sq = 0.f;
    for (int t = 0; t < nper; t++) { float dv = vals[t] - mu; sq += dv*dv; }
    red[u] = sq; __syncthreads();
    #pragma unroll
    for (int o = 64; o > 0; o >>= 1) { if (u < o) red[u] += red[u + o]; __syncthreads(); }
    float rstd = rsqrtf(red[0] / N + 1e-5f);
    float* o1 = out1 + (long)grp*o1Group + (long)rb*N;
    const float* gp = gam + (long)grp*gGroup;
    const float* bp = bet + (long)grp*gGroup;
    for (int t = 0; t < nper; t++) {
        int j = u + t*128;
        float y = (vals[t] - mu)*rstd*gp[j] + bp[j];
        o1[j] = y;
        if (out2) out2[(long)row*N + j] = y;
    }
}

__global__ void clear_k()
{
    long idx = (long)blockIdx.x*256 + threadIdx.x;
    if (idx < (long)U_*B_*d_) {
        g_pa[idx] = 0.f; g_pr[idx] = 0.f; g_dp[idx] = 0.f; g_sr[idx] = 0.f; g_gb[idx] = 0.f;
    }
}

// ---------------- host launcher ----------------
extern "C" void kernel_launch(void* const* d_in, const int* in_sizes, int n_in,
                              void* d_out, int out_size)
{
    const float* x          = (const float*)d_in[0];
    const float* mem0       = (const float*)d_in[1];
    const float* attn_in_w  = (const float*)d_in[2];
    const float* attn_in_b  = (const float*)d_in[3];
    const float* attn_out_w = (const float*)d_in[4];
    const float* attn_out_b = (const float*)d_in[5];
    const float* heb_w      = (const float*)d_in[6];
    const float* heb_rw     = (const float*)d_in[7];
    const float* alpha      = (const float*)d_in[8];
    const float* decay      = (const float*)d_in[9];
    const float* ln_act_g   = (const float*)d_in[10];
    const float* ln_act_b   = (const float*)d_in[11];
    const float* ln_rec_g   = (const float*)d_in[12];
    const float* ln_rec_b   = (const float*)d_in[13];
    const float* pred_w1    = (const float*)d_in[14];
    const float* pred_b1    = (const float*)d_in[15];
    const float* pred_w2    = (const float*)d_in[16];
    const float* pred_b2    = (const float*)d_in[17];
    const float* out_w      = (const float*)d_in[18];
    const float* out_b      = (const float*)d_in[19];
    const float* ln_out_g   = (const float*)d_in[20];
    const float* ln_out_b   = (const float*)d_in[21];

    float *pmem, *pqall, *pkv, *po, *ph, *ppa, *ppr, *pt1, *pnt, *ptmp,
          *poutpre, *pW, *pWr, *pasm, *pmod, *pC;
    cudaGetSymbolAddress((void**)&pmem,    g_mem);
    cudaGetSymbolAddress((void**)&pqall,   g_qall);
    cudaGetSymbolAddress((void**)&pkv,     g_kv);
    cudaGetSymbolAddress((void**)&po,      g_o);
    cudaGetSymbolAddress((void**)&ph,      g_h);
    cudaGetSymbolAddress((void**)&ppa,     g_pa);
    cudaGetSymbolAddress((void**)&ppr,     g_pr);
    cudaGetSymbolAddress((void**)&pt1,     g_t1);
    cudaGetSymbolAddress((void**)&pnt,     g_nt);
    cudaGetSymbolAddress((void**)&ptmp,    g_tmp);
    cudaGetSymbolAddress((void**)&poutpre, g_outpre);
    cudaGetSymbolAddress((void**)&pW,      g_W);
    cudaGetSymbolAddress((void**)&pWr,     g_Wr);
    cudaGetSymbolAddress((void**)&pasm,    g_asm);
    cudaGetSymbolAddress((void**)&pmod,    g_mod);
    cudaGetSymbolAddress((void**)&pC,      g_C);

    // side stream + events for graph-level fork/join (created once; deterministic)
    static cudaStream_t s1 = nullptr;
    static cudaEvent_t evFork = nullptr, evHeb = nullptr;
    if (!s1) {
        cudaStreamCreateWithFlags(&s1, cudaStreamNonBlocking);
        cudaEventCreateWithFlags(&evFork, cudaEventDisableTiming);
        cudaEventCreateWithFlags(&evHeb,  cudaEventDisableTiming);
    }
    cudaStream_t s0 = 0;

    const float qscale = 1.f / sqrtf((float)HD_);

    // init state (s0)
    cudaMemcpyAsync(pW,  heb_w,  sizeof(float)*(long)U_*d_*d_, cudaMemcpyDeviceToDevice, s0);
    cudaMemcpyAsync(pWr, heb_rw, sizeof(float)*(long)U_*d_*d_, cudaMemcpyDeviceToDevice, s0);
    cudaMemcpyAsync(pmem, mem0,  sizeof(float)*M_*B_*D_,       cudaMemcpyDeviceToDevice, s0);
    clear_k<<<(U_*B_*d_ + 255)/256, 256, 0, s0>>>();

    // q for all timesteps: per m, (T*B x 768) = x @ wq^T * qscale
    gemm2_k<0,0,false,true><<<dim3(12, 8, M_), 128, 0, s0>>>(x, 0, D_,
        attn_in_w, (long)3*D_*D_, 0, attn_in_b, (long)3*D_, nullptr, 0,
        pqall, (long)T_*B_*D_, D_, D_, qscale, 0);

    for (int t = 0; t < T_; t++) {
        // fork: s1 starts after everything previously enqueued on s0
        cudaEventRecord(evFork, s0);
        cudaStreamWaitEvent(s1, evFork, 0);

        // ---- Hebbian chain on s1 (independent of this step's attention) ----
        gemm2_k<0,0,false,false><<<dim3(6, 1, U_), 128, 0, s1>>>(ppa, (long)B_*d_, d_,
            pred_w1, (long)d_*d_, 0, pred_b1, (long)d_, nullptr, 0,
            pt1, (long)B_*d_, d_, d_, 1.f, 1);
        gemm2_k<0,0,false,false><<<dim3(18, 1, U_), 128, 0, s1>>>(pt1, (long)B_*d_, d_,
            pred_w2, (long)d_*3*d_, 0, pred_b2, (long)3*d_, nullptr, 0,
            pnt, (long)B_*3*d_, 3*d_, d_, 1.f, 0);
        gates_k<<<(U_*B_*d_ + 255)/256, 256, 0, s1>>>(alpha);
        rsm_k<<<dim3(U_*B_, 2), 128, 0, s1>>>();
        gemm2_k<0,0,true,false><<<dim3(6, 12, 2*U_), 128, 0, s1>>>(pasm, (long)B_*d_, d_,
            pmod, (long)B_*d_, U_, nullptr, 0, nullptr, 0,
            pC, (long)d_*d_, d_, B_, 1.f/B_, 0);
        wupd_k<<<dim3(d_, U_, 2), 128, 0, s1>>>(decay);
        gemm2_k<0,0,false,false><<<dim3(6, 1, U_), 128, 0, s1>>>(ppa, (long)B_*d_, d_,
            pWr, (long)d_*d_, 0, nullptr, 0, nullptr, 0,
            ptmp, (long)B_*d_, d_, d_, 1.f, 0);
        ln_k<<<U_*B_, 128, 0, s1>>>(ptmp, ppr, (long)B_*d_, nullptr,
            ln_rec_g, ln_rec_b, (long)d_, d_);
        cudaEventRecord(evHeb, s1);

        // ---- attention chain on s0 (concurrent with heb chain) ----
        gemm2_k<0,0,false,true><<<dim3(24, 8, M_), 128, 0, s0>>>(pmem, 0, D_,
            attn_in_w + (long)D_*D_, (long)3*D_*D_, 0, attn_in_b + D_, (long)3*D_, nullptr, 0,
            pkv, (long)KVROWS*KVN, KVN, D_, 1.f, 0);
        attn2_k<<<256, 256, 0, s0>>>(t);
        gemm2_k<0,1,false,true><<<dim3(12, 1, M_), 128, 0, s0>>>(po, (long)B_*D_, D_,
            attn_out_w, (long)D_*D_, 0, attn_out_b, (long)D_, nullptr, 0,
            ph, 0, D_, D_, 1.f, 0);

        // join: acts need h (s0) + pr/W (s1)
        cudaStreamWaitEvent(s0, evHeb, 0);

        for (int l = 0; l < L_; l++) {
            gemm2_k<0,0,false,false><<<dim3(6, 1, P_), 128, 0, s0>>>(ph, (long)B_*d_, d_,
                pW + (long)l*d_*d_, (long)L_*d_*d_, 0, nullptr, 0,
                ppr + (long)l*B_*d_, (long)L_*B_*d_,
                ptmp, (long)B_*d_, d_, d_, 1.f, 1);
            ln_k<<<P_*B_, 128, 0, s0>>>(ptmp, ppa + (long)l*B_*d_, (long)L_*B_*d_, ph,
                ln_act_g + (long)l*d_, ln_act_b + (long)l*d_, (long)L_*d_, d_);
        }

        gemm2_k<1,0,false,true><<<dim3(12, 1, M_), 128, 0, s0>>>(ph, 0, 0,
            out_w, (long)D_*D_, 0, out_b, (long)D_, nullptr, 0,
            poutpre, (long)B_*D_, D_, D_, 1.f, 0);
        ln_k<<<M_*B_, 128, 0, s0>>>(poutpre, pmem, (long)B_*D_, nullptr,
            ln_out_g, ln_out_b, (long)D_, D_);
    }

    cudaMemcpyAsync(d_out, pmem, sizeof(float)*M_*B_*D_, cudaMemcpyDeviceToDevice, s0);
}

// round 9
// speedup vs baseline: 1.7818x; 1.4576x over previous
#include <cuda_runtime.h>
#include <cstdint>
#include <math.h>

// Problem dims
#define T_ 8
#define B_ 32
#define D_ 768
#define M_ 8
#define S_ 2
#define L_ 2
#define H_ 8
#define HD_ 96
#define d_ 384
#define P_ 16          // M_*S_
#define U_ 32          // P_*L_

typedef unsigned long long u64;

// ---------------- device state / scratch ----------------
__device__ float g_mem[M_*B_*D_];
__device__ float g_qall[(long)M_*T_*B_*D_];
__device__ float g_qk[(long)M_*H_*T_*B_*D_];   // [ (m*8+h), t*B+b, 768 ]
__device__ float g_wmem[(long)M_*H_*B_*D_];    // [ (m*8+h), b, 768 ]
__device__ float g_o[M_*B_*D_];
__device__ float g_h[P_*B_*d_];
__device__ float g_pa[U_*B_*d_];
__device__ float g_pr[U_*B_*d_];
__device__ float g_dp[U_*B_*d_];
__device__ float g_sr[U_*B_*d_];
__device__ float g_gb[U_*B_*d_];
__device__ float g_W [(long)U_*d_*d_];
__device__ float g_Wr[(long)U_*d_*d_];
__device__ float g_t1[U_*B_*d_];
__device__ float g_nt[U_*B_*3*d_];
__device__ float g_mod[U_*B_*d_];
__device__ float g_asm[2*U_*B_*d_];
__device__ float g_C[(long)2*U_*d_*d_];
__device__ float g_tmp[U_*B_*d_];
__device__ float g_outpre[M_*B_*D_];

// ---------------- f32x2 helpers ----------------
__device__ __forceinline__ u64 pack2(float x, float y) {
    u64 r;
    asm("mov.b64 %0, {%1, %2};" : "=l"(r) : "f"(x), "f"(y));
    return r;
}
__device__ __forceinline__ void fma2(u64& d, u64 a, u64 b) {
    asm("fma.rn.f32x2 %0, %1, %2, %0;" : "+l"(d) : "l"(a), "l"(b));
}
__device__ __forceinline__ float2 unpack2(u64 v) {
    float2 f;
    asm("mov.b64 {%0, %1}, %2;" : "=f"(f.x), "=f"(f.y) : "l"(v));
    return f;
}

// ---------------- generic batched tiled GEMM (R4-proven f32x2, 4x4 tile) -----
// AMODE=0: Ab = A + z*aB, row stride lda
// AMODE=1: h-layout gather (A[( (z*2 + k/384)*B_ + i)*384 + k%384])
// AMODE=2: Ab = A + (z>>3)*aB + (z&7)*96, row stride lda
// wB2!=0 : Wb = W + (z>>3)*wB + (z&7)*wB2   (else zwrap / plain z batching)
#define AS_STRIDE 36
#define BS_STRIDE 68
template<int AMODE, int CMODE, bool TRANSA, bool TRANSB>
__global__ __launch_bounds__(128) void gemm2_k(
                        const float* __restrict__ A, long aB, int lda,
                        const float* __restrict__ W, long wB, int zwrap, long wB2,
                        const float* __restrict__ bias, long bB,
                        const float* __restrict__ add, long adB,
                        float* __restrict__ C, long cB,
                        int N, int K, float scale, int relu)
{
    __shared__ float As[16*AS_STRIDE];
    __shared__ float Bs[16*BS_STRIDE];
    const int tid = threadIdx.x;
    const int tx = tid & 15;
    const int ty = tid >> 4;
    const int z = blockIdx.z;
    const float* Ab;
    if (AMODE == 2) Ab = A + (long)(z >> 3)*aB + (long)(z & 7)*96;
    else            Ab = A + (long)z*aB;
    const float* Wb;
    if (wB2) Wb = W + (long)(z >> 3)*wB + (long)(z & 7)*wB2;
    else     Wb = W + (long)(zwrap ? (z % zwrap) : z)*wB;
    const int row0 = blockIdx.y*32, col0 = blockIdx.x*64;

    u64 acc[4][2];
    #pragma unroll
    for (int r = 0; r < 4; r++) { acc[r][0] = 0ull; acc[r][1] = 0ull; }

    for (int k0 = 0; k0 < K; k0 += 16) {
        if (TRANSA) {
            int kk = tid >> 3, r4 = (tid & 7)*4;
            float4 av = *(const float4*)&Ab[(long)(k0 + kk)*lda + row0 + r4];
            *(float4*)&As[kk*AS_STRIDE + r4] = av;
        } else {
            int r = tid >> 2, kc = (tid & 3)*4;
            float4 av;
            if (AMODE == 1) {
                int k = k0 + kc; int sh = k / d_, kr = k % d_;
                av = *(const float4*)&A[(((long)z*2 + sh)*B_ + row0 + r)*d_ + kr];
            } else {
                av = *(const float4*)&Ab[(long)(row0 + r)*lda + k0 + kc];
            }
            As[(kc+0)*AS_STRIDE + r] = av.x;
            As[(kc+1)*AS_STRIDE + r] = av.y;
            As[(kc+2)*AS_STRIDE + r] = av.z;
            As[(kc+3)*AS_STRIDE + r] = av.w;
        }
        #pragma unroll
        for (int it = 0; it < 2; it++) {
            int e = tid + it*128;
            if (TRANSB) {
                int j = e >> 2, kc = (e & 3)*4;
                float4 wv = *(const float4*)&Wb[(long)(col0 + j)*K + k0 + kc];
                Bs[(kc+0)*BS_STRIDE + j] = wv.x;
                Bs[(kc+1)*BS_STRIDE + j] = wv.y;
                Bs[(kc+2)*BS_STRIDE + j] = wv.z;
                Bs[(kc+3)*BS_STRIDE + j] = wv.w;
            } else {
                int kk = e >> 4, j4 = (e & 15)*4;
                float4 wv = *(const float4*)&Wb[(long)(k0 + kk)*N + col0 + j4];
                *(float4*)&Bs[kk*BS_STRIDE + j4] = wv;
            }
        }
        __syncthreads();
        #pragma unroll
        for (int kk = 0; kk < 16; kk++) {
            float4 a = *(const float4*)&As[kk*AS_STRIDE + ty*4];
            u64 b0 = *(const u64*)&Bs[kk*BS_STRIDE + tx*4];
            u64 b1 = *(const u64*)&Bs[kk*BS_STRIDE + tx*4 + 2];
            u64 a0 = pack2(a.x, a.x);
            u64 a1 = pack2(a.y, a.y);
            u64 a2 = pack2(a.z, a.z);
            u64 a3 = pack2(a.w, a.w);
            fma2(acc[0][0], a0, b0); fma2(acc[0][1], a0, b1);
            fma2(acc[1][0], a1, b0); fma2(acc[1][1], a1, b1);
            fma2(acc[2][0], a2, b0); fma2(acc[2][1], a2, b1);
            fma2(acc[3][0], a3, b0); fma2(acc[3][1], a3, b1);
        }
        __syncthreads();
    }

    float* Cb = C + (long)z*cB;
    const int colb = col0 + tx*4;
    #pragma unroll
    for (int r = 0; r < 4; r++) {
        int row = row0 + ty*4 + r;
        float2 v0 = unpack2(acc[r][0]);
        float2 v1 = unpack2(acc[r][1]);
        float v[4] = {v0.x, v0.y, v1.x, v1.y};
        #pragma unroll
        for (int c = 0; c < 4; c++) {
            if (bias) v[c] += bias[(long)z*bB + colb + c];
            v[c] *= scale;
            if (add)  v[c] += add[(long)z*adB + (long)row*N + colb + c];
            if (relu) v[c] = fmaxf(v[c], 0.f);
        }
        if (CMODE) {
            int sh = colb / d_, jr = colb % d_;
            float* dst = C + (((long)z*2 + sh)*B_ + row)*d_ + jr;
            *(float4*)dst = make_float4(v[0], v[1], v[2], v[3]);
        } else {
            *(float4*)&Cb[(long)row*N + colb] = make_float4(v[0], v[1], v[2], v[3]);
        }
    }
}

// ---------------- fused scores + softmax + weighted-mem  ---------------------
// block (b, m), 256 threads (warp w = head h).
// score[s] = qk[m,h,(t,b),:] . mem[s,b,:]    (bk term cancels in softmax)
// wmem[m,h,b,:] = sum_s softmax(score)[s] * mem[s,b,:]
__global__ __launch_bounds__(256) void wmem_k(int t)
{
    int b = blockIdx.x, m = blockIdx.y;
    int tid = threadIdx.x;
    int w = tid >> 5, lane = tid & 31;
    __shared__ float memsh[M_*D_];
    __shared__ float scr[H_*M_];

    // load mem[:, b, :] (8 x 768)
    #pragma unroll
    for (int i = 0; i < 6; i++) {
        int fe = tid + i*256;            // float4 index, 1536 total
        int s = fe / 192, j4 = (fe % 192)*4;
        *(float4*)&memsh[s*D_ + j4] = *(const float4*)&g_mem[((long)s*B_ + b)*D_ + j4];
    }
    __syncthreads();

    const float* qkrow = g_qk + (((long)(m*H_ + w))*T_*B_ + t*B_ + b)*D_;
    float qv[24];
    #pragma unroll
    for (int i = 0; i < 24; i++) qv[i] = qkrow[lane + i*32];

    for (int s = 0; s < M_; s++) {
        float p = 0.f;
        #pragma unroll
        for (int i = 0; i < 24; i++) p += qv[i]*memsh[s*D_ + lane + i*32];
        #pragma unroll
        for (int o = 16; o > 0; o >>= 1) p += __shfl_xor_sync(0xffffffffu, p, o);
        if (lane == 0) scr[w*M_ + s] = p;
    }
    __syncwarp();

    float a[M_];
    float mx = -1e30f;
    #pragma unroll
    for (int s = 0; s < M_; s++) mx = fmaxf(mx, scr[w*M_ + s]);
    float sum = 0.f;
    #pragma unroll
    for (int s = 0; s < M_; s++) { a[s] = __expf(scr[w*M_ + s] - mx); sum += a[s]; }
    float inv = 1.f / sum;
    #pragma unroll
    for (int s = 0; s < M_; s++) a[s] *= inv;

    float* dst = g_wmem + (((long)(m*H_ + w))*B_ + b)*D_;
    #pragma unroll
    for (int i = 0; i < 24; i++) {
        int j = lane + i*32;
        float acc = 0.f;
        #pragma unroll
        for (int s = 0; s < M_; s++) acc += a[s]*memsh[s*D_ + j];
        dst[j] = acc;
    }
}

// ---------------- per-head V projection: o = wmem @ Wv_h^T + bv_h ------------
// z = (m*8+h); A = wmem[z] (32 x 768); W rows (2D + h*96 + j) of attn_in_w[m];
// C: g_o[(m*32+b)*768 + h*96 + col]. Tile BM32 x BN32 x BK16; 128 threads.
__global__ __launch_bounds__(128) void attnv_k(const float* __restrict__ w,
                                               const float* __restrict__ bias)
{
    __shared__ float As[16*36];
    __shared__ float Bs[16*36];
    const int tid = threadIdx.x;
    const int tx = tid & 7;        // 4 cols each
    const int ty = tid >> 3;       // 2 rows each (0..15)
    const int z = blockIdx.z, m = z >> 3, h = z & 7;
    const int col0 = blockIdx.x*32;
    const float* Ab = g_wmem + (long)z*B_*D_;
    const float* Wb = w + (long)m*3*D_*D_ + (long)(2*D_ + h*HD_)*D_;

    u64 acc[2][2];
    acc[0][0] = acc[0][1] = acc[1][0] = acc[1][1] = 0ull;

    for (int k0 = 0; k0 < D_; k0 += 16) {
        {
            int r = tid >> 2, kc = (tid & 3)*4;
            float4 av = *(const float4*)&Ab[(long)r*D_ + k0 + kc];
            As[(kc+0)*36 + r] = av.x;
            As[(kc+1)*36 + r] = av.y;
            As[(kc+2)*36 + r] = av.z;
            As[(kc+3)*36 + r] = av.w;
        }
        {
            int j = tid >> 2, kc = (tid & 3)*4;
            float4 wv = *(const float4*)&Wb[(long)(col0 + j)*D_ + k0 + kc];
            Bs[(kc+0)*36 + j] = wv.x;
            Bs[(kc+1)*36 + j] = wv.y;
            Bs[(kc+2)*36 + j] = wv.z;
            Bs[(kc+3)*36 + j] = wv.w;
        }
        __syncthreads();
        #pragma unroll
        for (int kk = 0; kk < 16; kk++) {
            float2 a = *(const float2*)&As[kk*36 + ty*2];
            u64 b0 = *(const u64*)&Bs[kk*36 + tx*4];
            u64 b1 = *(const u64*)&Bs[kk*36 + tx*4 + 2];
            u64 a0 = pack2(a.x, a.x);
            u64 a1 = pack2(a.y, a.y);
            fma2(acc[0][0], a0, b0); fma2(acc[0][1], a0, b1);
            fma2(acc[1][0], a1, b0); fma2(acc[1][1], a1, b1);
        }
        __syncthreads();
    }

    const float* bb = bias + (long)m*3*D_ + 2*D_ + h*HD_ + col0 + tx*4;
    #pragma unroll
    for (int r = 0; r < 2; r++) {
        int row = ty*2 + r;
        float2 v0 = unpack2(acc[r][0]);
        float2 v1 = unpack2(acc[r][1]);
        float4 v = make_float4(v0.x + bb[0], v0.y + bb[1], v1.x + bb[2], v1.y + bb[3]);
        *(float4*)&g_o[((long)m*B_ + row)*D_ + h*HD_ + col0 + tx*4] = v;
    }
}

// ---------------- plastic layer kernels (batched over U_ units) --------------
__global__ void gates_k(const float* __restrict__ alpha)
{
    int idx = blockIdx.x*256 + threadIdx.x;
    if (idx >= U_*B_*d_) return;
    int j = idx % d_; int b = (idx/d_) % B_; int u = idx/(B_*d_);
    const float* nt = g_nt + ((long)(u*B_ + b))*3*d_ + j*3;
    float pd = nt[0], ps = nt[1], pg = nt[2];
    float inv = 1.f / fmaxf(ps, 1e-6f);
    float dpv = tanhf(g_dp[idx] + pd*inv);
    float srv = 1.f/(1.f + __expf(-(g_sr[idx] + ps)));
    float gbv = 1.f/(1.f + __expf(-(g_gb[idx] + pg*inv)));
    g_dp[idx] = dpv; g_sr[idx] = srv; g_gb[idx] = gbv;
    g_mod[idx] = alpha[(long)u*d_ + j] * dpv * srv;
}

__global__ void rsm_k()
{
    int row = blockIdx.x;
    int which = blockIdx.y;
    const float* src = (which ? g_pr : g_pa) + (long)row*d_;
    float* dst = g_asm + (long)which*U_*B_*d_ + (long)row*d_;
    int u = threadIdx.x;
    __shared__ float red[128];
    float v0 = src[u], v1 = src[u + 128], v2 = src[u + 256];
    float mx = fmaxf(v0, fmaxf(v1, v2));
    red[u] = mx; __syncthreads();
    #pragma unroll
    for (int o = 64; o > 0; o >>= 1) { if (u < o) red[u] = fmaxf(red[u], red[u + o]); __syncthreads(); }
    mx = red[0]; __syncthreads();
    float e0 = __expf(v0 - mx), e1 = __expf(v1 - mx), e2 = __expf(v2 - mx);
    red[u] = e0 + e1 + e2; __syncthreads();
    #pragma unroll
    for (int o = 64; o > 0; o >>= 1) { if (u < o) red[u] += red[u + o]; __syncthreads(); }
    float inv = 1.f / red[0];
    dst[u] = e0*inv; dst[u + 128] = e1*inv; dst[u + 256] = e2*inv;
}

__global__ void wupd_k(const float* __restrict__ decay)
{
    int i = blockIdx.x, u = blockIdx.y, which = blockIdx.z;
    float* Wp = (which ? g_Wr : g_W) + ((long)u*d_ + i)*d_;
    const float* Cp = g_C + ((long)(which*U_ + u)*d_ + i)*d_;
    int t = threadIdx.x;
    __shared__ float red[128];
    __shared__ float sdsh;
    if (t < 32) {
        float v = g_gb[((long)u*B_ + t)*d_ + i];
        #pragma unroll
        for (int o = 16; o > 0; o >>= 1) v += __shfl_xor_sync(0xffffffffu, v, o);
        if (t == 0) {
            float s = v*(1.f/B_);
            sdsh = decay[(long)u*d_ + i] * (1.f/(1.f + __expf(-s)));
        }
    }
    float w0 = Wp[t], w1 = Wp[t + 128], w2 = Wp[t + 256];
    float mx = fmaxf(w0, fmaxf(w1, w2));
    red[t] = mx; __syncthreads();
    #pragma unroll
    for (int o = 64; o > 0; o >>= 1) { if (t < o) red[t] = fmaxf(red[t], red[t + o]); __syncthreads(); }
    mx = red[0]; __syncthreads();
    float e0 = __expf(w0 - mx), e1 = __expf(w1 - mx), e2 = __expf(w2 - mx);
    red[t] = e0 + e1 + e2; __syncthreads();
    #pragma unroll
    for (int o = 64; o > 0; o >>= 1) { if (t < o) red[t] += red[t + o]; __syncthreads(); }
    float invs = 1.f / red[0];
    float om = 1.f - sdsh;
    Wp[t]       = w0*om + e0*invs*Cp[t];
    Wp[t + 128] = w1*om + e1*invs*Cp[t + 128];
    Wp[t + 256] = w2*om + e2*invs*Cp[t + 256];
}

// ---------------- LayerNorm ----------------
__global__ void ln_k(const float* __restrict__ in,
                     float* __restrict__ out1, long o1Group,
                     float* __restrict__ out2,
                     const float* __restrict__ gam, const float* __restrict__ bet,
                     long gGroup, int N)
{
    int row = blockIdx.x;
    int u = threadIdx.x;
    int grp = row / B_, rb = row % B_;
    const float* x = in + (long)row*N;
    int nper = N / 128;
    float vals[6];
    float s = 0.f;
    for (int t = 0; t < nper; t++) { vals[t] = x[u + t*128]; s += vals[t]; }
    __shared__ float red[128];
    red[u] = s; __syncthreads();
    #pragma unroll
    for (int o = 64; o > 0; o >>= 1) { if (u < o) red[u] += red[u + o]; __syncthreads(); }
    float mu = red[0] / N; __syncthreads();
    float sq = 0.f;
    for (int t = 0; t < nper; t++) { float dv = vals[t] - mu; sq += dv*dv; }
    red[u] = sq; __syncthreads();
    #pragma unroll
    for (int o = 64; o > 0; o >>= 1) { if (u < o) red[u] += red[u + o]; __syncthreads(); }
    float rstd = rsqrtf(red[0] / N + 1e-5f);
    float* o1 = out1 + (long)grp*o1Group + (long)rb*N;
    const float* gp = gam + (long)grp*gGroup;
    const float* bp = bet + (long)grp*gGroup;
    for (int t = 0; t < nper; t++) {
        int j = u + t*128;
        float y = (vals[t] - mu)*rstd*gp[j] + bp[j];
        o1[j] = y;
        if (out2) out2[(long)row*N + j] = y;
    }
}

__global__ void clear_k()
{
    long idx = (long)blockIdx.x*256 + threadIdx.x;
    if (idx < (long)U_*B_*d_) {
        g_pa[idx] = 0.f; g_pr[idx] = 0.f; g_dp[idx] = 0.f; g_sr[idx] = 0.f; g_gb[idx] = 0.f;
    }
}

// ---------------- host launcher ----------------
extern "C" void kernel_launch(void* const* d_in, const int* in_sizes, int n_in,
                              void* d_out, int out_size)
{
    const float* x          = (const float*)d_in[0];
    const float* mem0       = (const float*)d_in[1];
    const float* attn_in_w  = (const float*)d_in[2];
    const float* attn_in_b  = (const float*)d_in[3];
    const float* attn_out_w = (const float*)d_in[4];
    const float* attn_out_b = (const float*)d_in[5];
    const float* heb_w      = (const float*)d_in[6];
    const float* heb_rw     = (const float*)d_in[7];
    const float* alpha      = (const float*)d_in[8];
    const float* decay      = (const float*)d_in[9];
    const float* ln_act_g   = (const float*)d_in[10];
    const float* ln_act_b   = (const float*)d_in[11];
    const float* ln_rec_g   = (const float*)d_in[12];
    const float* ln_rec_b   = (const float*)d_in[13];
    const float* pred_w1    = (const float*)d_in[14];
    const float* pred_b1    = (const float*)d_in[15];
    const float* pred_w2    = (const float*)d_in[16];
    const float* pred_b2    = (const float*)d_in[17];
    const float* out_w      = (const float*)d_in[18];
    const float* out_b      = (const float*)d_in[19];
    const float* ln_out_g   = (const float*)d_in[20];
    const float* ln_out_b   = (const float*)d_in[21];

    float *pmem, *pqall, *pqk, *po, *ph, *ppa, *ppr, *pt1, *pnt, *ptmp,
          *poutpre, *pW, *pWr, *pasm, *pmod, *pC;
    cudaGetSymbolAddress((void**)&pmem,    g_mem);
    cudaGetSymbolAddress((void**)&pqall,   g_qall);
    cudaGetSymbolAddress((void**)&pqk,     g_qk);
    cudaGetSymbolAddress((void**)&po,      g_o);
    cudaGetSymbolAddress((void**)&ph,      g_h);
    cudaGetSymbolAddress((void**)&ppa,     g_pa);
    cudaGetSymbolAddress((void**)&ppr,     g_pr);
    cudaGetSymbolAddress((void**)&pt1,     g_t1);
    cudaGetSymbolAddress((void**)&pnt,     g_nt);
    cudaGetSymbolAddress((void**)&ptmp,    g_tmp);
    cudaGetSymbolAddress((void**)&poutpre, g_outpre);
    cudaGetSymbolAddress((void**)&pW,      g_W);
    cudaGetSymbolAddress((void**)&pWr,     g_Wr);
    cudaGetSymbolAddress((void**)&pasm,    g_asm);
    cudaGetSymbolAddress((void**)&pmod,    g_mod);
    cudaGetSymbolAddress((void**)&pC,      g_C);

    static cudaStream_t s1 = nullptr;
    static cudaEvent_t evFork = nullptr, evHeb = nullptr;
    if (!s1) {
        cudaStreamCreateWithFlags(&s1, cudaStreamNonBlocking);
        cudaEventCreateWithFlags(&evFork, cudaEventDisableTiming);
        cudaEventCreateWithFlags(&evHeb,  cudaEventDisableTiming);
    }
    cudaStream_t s0 = 0;

    const float qscale = 1.f / sqrtf((float)HD_);

    // init state (s0)
    cudaMemcpyAsync(pW,  heb_w,  sizeof(float)*(long)U_*d_*d_, cudaMemcpyDeviceToDevice, s0);
    cudaMemcpyAsync(pWr, heb_rw, sizeof(float)*(long)U_*d_*d_, cudaMemcpyDeviceToDevice, s0);
    cudaMemcpyAsync(pmem, mem0,  sizeof(float)*M_*B_*D_,       cudaMemcpyDeviceToDevice, s0);
    clear_k<<<(U_*B_*d_ + 255)/256, 256, 0, s0>>>();

    // q for all timesteps: per m, (T*B x 768) = x @ wq^T * qscale
    gemm2_k<0,0,false,true><<<dim3(12, 8, M_), 128, 0, s0>>>(x, 0, D_,
        attn_in_w, (long)3*D_*D_, 0, 0, attn_in_b, (long)3*D_, nullptr, 0,
        pqall, (long)T_*B_*D_, D_, D_, qscale, 0);
    // qk[m,h] = qh(h-slice) @ Wk(h-slice rows)   [256 x 768, K=96], z = m*8+h
    gemm2_k<2,0,false,false><<<dim3(12, 8, M_*H_), 128, 0, s0>>>(pqall, (long)T_*B_*D_, D_,
        attn_in_w + (long)D_*D_, (long)3*D_*D_, 0, (long)HD_*D_,
        nullptr, 0, nullptr, 0,
        pqk, (long)T_*B_*D_, D_, HD_, 1.f, 0);

    for (int t = 0; t < T_; t++) {
        cudaEventRecord(evFork, s0);
        cudaStreamWaitEvent(s1, evFork, 0);

        // ---- Hebbian chain on s1 ----
        gemm2_k<0,0,false,false><<<dim3(6, 1, U_), 128, 0, s1>>>(ppa, (long)B_*d_, d_,
            pred_w1, (long)d_*d_, 0, 0, pred_b1, (long)d_, nullptr, 0,
            pt1, (long)B_*d_, d_, d_, 1.f, 1);
        gemm2_k<0,0,false,false><<<dim3(18, 1, U_), 128, 0, s1>>>(pt1, (long)B_*d_, d_,
            pred_w2, (long)d_*3*d_, 0, 0, pred_b2, (long)3*d_, nullptr, 0,
            pnt, (long)B_*3*d_, 3*d_, d_, 1.f, 0);
        gates_k<<<(U_*B_*d_ + 255)/256, 256, 0, s1>>>(alpha);
        rsm_k<<<dim3(U_*B_, 2), 128, 0, s1>>>();
        gemm2_k<0,0,true,false><<<dim3(6, 12, 2*U_), 128, 0, s1>>>(pasm, (long)B_*d_, d_,
            pmod, (long)B_*d_, U_, 0, nullptr, 0, nullptr, 0,
            pC, (long)d_*d_, d_, B_, 1.f/B_, 0);
        wupd_k<<<dim3(d_, U_, 2), 128, 0, s1>>>(decay);
        gemm2_k<0,0,false,false><<<dim3(6, 1, U_), 128, 0, s1>>>(ppa, (long)B_*d_, d_,
            pWr, (long)d_*d_, 0, 0, nullptr, 0, nullptr, 0,
            ptmp, (long)B_*d_, d_, d_, 1.f, 0);
        ln_k<<<U_*B_, 128, 0, s1>>>(ptmp, ppr, (long)B_*d_, nullptr,
            ln_rec_g, ln_rec_b, (long)d_, d_);
        cudaEventRecord(evHeb, s1);

        // ---- attention chain on s0 (restructured: no kv GEMM) ----
        wmem_k<<<dim3(B_, M_), 256, 0, s0>>>(t);
        attnv_k<<<dim3(3, 1, M_*H_), 128, 0, s0>>>(attn_in_w, attn_in_b);
        // h = scatter( o @ out_w^T + out_b )
        gemm2_k<0,1,false,true><<<dim3(12, 1, M_), 128, 0, s0>>>(po, (long)B_*D_, D_,
            attn_out_w, (long)D_*D_, 0, 0, attn_out_b, (long)D_, nullptr, 0,
            ph, 0, D_, D_, 1.f, 0);

        cudaStreamWaitEvent(s0, evHeb, 0);

        for (int l = 0; l < L_; l++) {
            gemm2_k<0,0,false,false><<<dim3(6, 1, P_), 128, 0, s0>>>(ph, (long)B_*d_, d_,
                pW + (long)l*d_*d_, (long)L_*d_*d_, 0, 0, nullptr, 0,
                ppr + (long)l*B_*d_, (long)L_*B_*d_,
                ptmp, (long)B_*d_, d_, d_, 1.f, 1);
            ln_k<<<P_*B_, 128, 0, s0>>>(ptmp, ppa + (long)l*B_*d_, (long)L_*B_*d_, ph,
                ln_act_g + (long)l*d_, ln_act_b + (long)l*d_, (long)L_*d_, d_);
        }

        gemm2_k<1,0,false,true><<<dim3(12, 1, M_), 128, 0, s0>>>(ph, 0, 0,
            out_w, (long)D_*D_, 0, 0, out_b, (long)D_, nullptr, 0,
            poutpre, (long)B_*D_, D_, D_, 1.f, 0);
        ln_k<<<M_*B_, 128, 0, s0>>>(poutpre, pmem, (long)B_*D_, nullptr,
            ln_out_g, ln_out_b, (long)D_, D_);
    }

    cudaMemcpyAsync(d_out, pmem, sizeof(float)*M_*B_*D_, cudaMemcpyDeviceToDevice, s0);
}